// round 1
// baseline (speedup 1.0000x reference)
#include <cuda_runtime.h>
#include <math.h>

#define B_   32
#define T_   4096
#define C_   1024
#define D_   64
#define TA_  2048   // even tokens
#define TB_  2048   // odd tokens
#define R_   1024   // merged count
#define TUN_ 1024   // unmerged count (TA - R)
#define TOUT_ 3072  // TUN + TB

// ---------------- scratch (static device globals; no runtime alloc) ----------------
__device__ float g_m[(size_t)B_ * T_ * D_];     // normalized metric, 33.5 MB
__device__ float g_nmax[B_ * TA_];
__device__ int   g_nidx[B_ * TA_];
__device__ int   g_unm [B_ * TUN_];
__device__ int   g_off [B_ * (TB_ + 1)];
__device__ int   g_csr [B_ * R_];

#define NEG_INF __int_as_float(0xff800000)

// ---------------- K1: normalize metric rows (one warp per row) ----------------
__global__ __launch_bounds__(256) void k_normalize(const float* __restrict__ metric) {
    int warp = (blockIdx.x * blockDim.x + threadIdx.x) >> 5;
    int lane = threadIdx.x & 31;
    if (warp >= B_ * T_) return;
    const float* row = metric + (size_t)warp * D_;
    float v0 = row[lane];
    float v1 = row[lane + 32];
    float s = v0 * v0 + v1 * v1;
#pragma unroll
    for (int o = 16; o > 0; o >>= 1) s += __shfl_xor_sync(0xffffffffu, s, o);
    float nrm = __fsqrt_rn(s);
    g_m[(size_t)warp * D_ + lane]      = __fdiv_rn(v0, nrm);
    g_m[(size_t)warp * D_ + lane + 32] = __fdiv_rn(v1, nrm);
}

// ---------------- K2: fused GEMM + row max/argmax ----------------
// Per block: 128 i-rows x (loop over 16 j-tiles of 128). 256 threads, 8x8 per thread.
// Tiles stored k-major (As[k][i], Bs[k][j], pitch 132) so inner loop uses float4 LDS.
__global__ __launch_bounds__(256) void k_argmax() {
    extern __shared__ float sm[];
    float (*As)[132] = (float (*)[132])sm;
    float (*Bs)[132] = (float (*)[132])(sm + 64 * 132);

    const int b  = blockIdx.y;
    const int i0 = blockIdx.x * 128;
    const float* mb = g_m + (size_t)b * T_ * D_;
    const int tid = threadIdx.x;

    // load A tile (even tokens), transpose to k-major
    for (int idx = tid; idx < 128 * 64; idx += 256) {
        int r = idx >> 6, c = idx & 63;
        As[c][r] = mb[(size_t)(2 * (i0 + r)) * D_ + c];
    }

    const int tx = tid & 15, ty = tid >> 4;
    float best[8];
    int   bidx[8];
#pragma unroll
    for (int u = 0; u < 8; u++) { best[u] = NEG_INF; bidx[u] = 0; }

    for (int jt = 0; jt < TB_ / 128; jt++) {
        __syncthreads();
        for (int idx = tid; idx < 128 * 64; idx += 256) {
            int r = idx >> 6, c = idx & 63;
            Bs[c][r] = mb[(size_t)(2 * (jt * 128 + r) + 1) * D_ + c];
        }
        __syncthreads();

        float acc[8][8];
#pragma unroll
        for (int u = 0; u < 8; u++)
#pragma unroll
            for (int v = 0; v < 8; v++) acc[u][v] = 0.0f;

#pragma unroll 8
        for (int k = 0; k < 64; k++) {
            float4 a0 = *(const float4*)&As[k][4 * ty];
            float4 a1 = *(const float4*)&As[k][64 + 4 * ty];
            float4 b0 = *(const float4*)&Bs[k][4 * tx];
            float4 b1 = *(const float4*)&Bs[k][64 + 4 * tx];
            float av[8] = {a0.x, a0.y, a0.z, a0.w, a1.x, a1.y, a1.z, a1.w};
            float bv[8] = {b0.x, b0.y, b0.z, b0.w, b1.x, b1.y, b1.z, b1.w};
#pragma unroll
            for (int u = 0; u < 8; u++)
#pragma unroll
                for (int v = 0; v < 8; v++)
                    acc[u][v] = fmaf(av[u], bv[v], acc[u][v]);
        }

        // running max; iterate v ascending so within-thread j is ascending
        // (strict > keeps the first occurrence, matching jnp.argmax)
#pragma unroll
        for (int v = 0; v < 8; v++) {
            int j = jt * 128 + ((v < 4) ? (4 * tx + v) : (64 + 4 * tx + (v - 4)));
#pragma unroll
            for (int u = 0; u < 8; u++) {
                if (acc[u][v] > best[u]) { best[u] = acc[u][v]; bidx[u] = j; }
            }
        }
    }

    // reduce across the 16 threads (tx) sharing each i; tie-break: smaller j
#pragma unroll
    for (int u = 0; u < 8; u++) {
        float v = best[u];
        int   id = bidx[u];
#pragma unroll
        for (int o = 8; o > 0; o >>= 1) {
            float ov = __shfl_xor_sync(0xffffffffu, v, o);
            int   oi = __shfl_xor_sync(0xffffffffu, id, o);
            if (ov > v || (ov == v && oi < id)) { v = ov; id = oi; }
        }
        if (tx == 0) {
            int i = i0 + ((u < 4) ? (4 * ty + u) : (64 + 4 * ty + (u - 4)));
            if (i == 0) { v = NEG_INF; id = 0; }  // scores[:,0,:] = -inf
            g_nmax[b * TA_ + i] = v;
            g_nidx[b * TA_ + i] = id;
        }
    }
}

// ---------------- K3: per-batch selection + CSR build (one block per batch) ----------------
__device__ __forceinline__ void bitonic_ull(unsigned long long* a, int n) {
    const int tid = threadIdx.x;
    for (int k = 2; k <= n; k <<= 1) {
        for (int j = k >> 1; j > 0; j >>= 1) {
            __syncthreads();
            for (int i = tid; i < n; i += 1024) {
                int ixj = i ^ j;
                if (ixj > i) {
                    unsigned long long p = a[i], q = a[ixj];
                    bool asc = ((i & k) == 0);
                    if ((p > q) == asc) { a[i] = q; a[ixj] = p; }
                }
            }
        }
    }
    __syncthreads();
}

__global__ __launch_bounds__(1024, 1) void k_select() {
    __shared__ unsigned long long key[2048];
    __shared__ int s_src[1024];
    __shared__ int s_dst[1024];
    const int b = blockIdx.x;
    const int tid = threadIdx.x;

    // key = (~sortable(node_max), idx): ascending sort == (value desc, idx asc)
    // == stable jnp.argsort(-node_max)
    for (int e = tid; e < 2048; e += 1024) {
        unsigned int u = __float_as_uint(g_nmax[b * TA_ + e]);
        u = (u & 0x80000000u) ? ~u : (u | 0x80000000u);
        key[e] = ((unsigned long long)(~u) << 32) | (unsigned int)e;
    }
    bitonic_ull(key, 2048);

    int src_i = (int)(key[tid] & 0xffffffffu);          // rank < r : merged
    int unm_i = (int)(key[1024 + tid] & 0xffffffffu);   // rank >= r: unmerged
    s_src[tid] = src_i;
    s_dst[tid] = g_nidx[b * TA_ + src_i];
    __syncthreads();

    // sort unm indices ascending
    key[tid] = (unsigned long long)(unsigned int)unm_i;
    bitonic_ull(key, 1024);
    g_unm[b * TUN_ + tid] = (int)(key[tid] & 0xffffffffu);
    __syncthreads();

    // sort (dst, rank k) pairs -> CSR grouped by dst, stable in k (deterministic fp order)
    key[tid] = ((unsigned long long)(((unsigned)s_dst[tid] << 10) | (unsigned)tid) << 32)
             | (unsigned int)s_src[tid];
    bitonic_ull(key, 1024);

    int d     = (int)((unsigned)(key[tid] >> 32) >> 10);
    int dprev = (tid == 0) ? -1 : (int)((unsigned)(key[tid - 1] >> 32) >> 10);
    for (int j = dprev + 1; j <= d; j++) g_off[b * (TB_ + 1) + j] = tid;
    if (tid == 1023)
        for (int j = d + 1; j <= TB_; j++) g_off[b * (TB_ + 1) + j] = 1024;
    g_csr[b * R_ + tid] = (int)(key[tid] & 0xffffffffu);
}

// ---------------- K4: gather + merge + divide (one block per output row) ----------------
__global__ __launch_bounds__(256) void k_merge(const float* __restrict__ x,
                                               float* __restrict__ out) {
    int rb = blockIdx.x;
    int b  = rb / TOUT_;
    int r  = rb - b * TOUT_;
    int t  = threadIdx.x;   // 256 threads x float4 = 1024 floats
    const float* xb = x + (size_t)b * T_ * C_;
    float4* orow = (float4*)(out + (size_t)((size_t)b * TOUT_ + r) * C_);

    if (r < TUN_) {
        int src = g_unm[b * TUN_ + r];
        orow[t] = ((const float4*)(xb + (size_t)(2 * src) * C_))[t];
    } else {
        int j = r - TUN_;
        int s = g_off[b * (TB_ + 1) + j];
        int e = g_off[b * (TB_ + 1) + j + 1];
        float4 acc = ((const float4*)(xb + (size_t)(2 * j + 1) * C_))[t];
        for (int p = s; p < e; p++) {
            int src = g_csr[b * R_ + p];
            float4 v = ((const float4*)(xb + (size_t)(2 * src) * C_))[t];
            acc.x += v.x; acc.y += v.y; acc.z += v.z; acc.w += v.w;
        }
        float sz = (float)(1 + e - s);
        acc.x = __fdiv_rn(acc.x, sz);
        acc.y = __fdiv_rn(acc.y, sz);
        acc.z = __fdiv_rn(acc.z, sz);
        acc.w = __fdiv_rn(acc.w, sz);
        orow[t] = acc;
    }
}

// ---------------- launcher ----------------
extern "C" void kernel_launch(void* const* d_in, const int* in_sizes, int n_in,
                              void* d_out, int out_size) {
    const float* x = nullptr;
    const float* metric = nullptr;
    for (int i = 0; i < n_in; i++) {
        long long sz = in_sizes[i];
        if (sz == (long long)B_ * T_ * C_)      x = (const float*)d_in[i];
        else if (sz == (long long)B_ * T_ * D_) metric = (const float*)d_in[i];
    }
    float* out = (float*)d_out;

    k_normalize<<<(B_ * T_) / 8, 256>>>(metric);

    const int smem_bytes = 2 * 64 * 132 * (int)sizeof(float);  // 67.6 KB
    cudaFuncSetAttribute(k_argmax, cudaFuncAttributeMaxDynamicSharedMemorySize, smem_bytes);
    dim3 g2(TA_ / 128, B_);
    k_argmax<<<g2, 256, smem_bytes>>>();

    k_select<<<B_, 1024>>>();

    k_merge<<<B_ * TOUT_, 256>>>(x, out);
}